// round 5
// baseline (speedup 1.0000x reference)
#include <cuda_runtime.h>
#include <cuda_bf16.h>
#include <math.h>
#include <cstdint>

// Problem constants
#define BB   8
#define CCH  512
#define C8   64
#define NN   2048
#define OUT_OFF (BB*CCH*NN)   // start of attention region in d_out (floats)

typedef unsigned long long u64;

// Scratch: q/k as 2-way bf16 split [b][n][comp*64 + o], comp 0=hi, 1=mid
__device__ __nv_bfloat16 g_qs[BB*NN*128];
__device__ __nv_bfloat16 g_ks[BB*NN*128];
__device__ float g_v[BB*CCH*NN];           // slow path only (gamma != 0)
__device__ float g_av[BB*CCH*NN];          // slow path only

// ---- sm_80-class tensor helpers (legal on plain sm_103 target) -----------
__device__ __forceinline__ uint32_t smem_u32(const void* p) {
    uint32_t a;
    asm("{ .reg .u64 t; cvta.to.shared.u64 t, %1; cvt.u32.u64 %0, t; }" : "=r"(a) : "l"(p));
    return a;
}
#define LDSM_X4(r0, r1, r2, r3, addr) \
    asm volatile("ldmatrix.sync.aligned.m8n8.x4.shared.b16 {%0,%1,%2,%3}, [%4];" \
        : "=r"(r0), "=r"(r1), "=r"(r2), "=r"(r3) : "r"(addr))
#define LDSM_X2(r0, r1, addr) \
    asm volatile("ldmatrix.sync.aligned.m8n8.x2.shared.b16 {%0,%1}, [%2];" \
        : "=r"(r0), "=r"(r1) : "r"(addr))
#define CP_ASYNC16(dst, src) \
    asm volatile("cp.async.cg.shared.global [%0], [%1], 16;" :: "r"(dst), "l"(src) : "memory")
#define CP_COMMIT() asm volatile("cp.async.commit_group;" ::: "memory")

__device__ __forceinline__ void mma_bf16(float& c0, float& c1, float& c2, float& c3,
                                         uint32_t a0, uint32_t a1, uint32_t a2, uint32_t a3,
                                         uint32_t b0, uint32_t b1) {
    asm volatile(
        "mma.sync.aligned.m16n8k16.row.col.f32.bf16.bf16.f32 "
        "{%0,%1,%2,%3}, {%4,%5,%6,%7}, {%8,%9}, {%0,%1,%2,%3};"
        : "+f"(c0), "+f"(c1), "+f"(c2), "+f"(c3)
        : "r"(a0), "r"(a1), "r"(a2), "r"(a3), "r"(b0), "r"(b1));
}

__device__ __forceinline__ uint32_t us_of(__nv_bfloat16 h) {
    return (uint32_t)__bfloat16_as_ushort(h);
}

// ---------------------------------------------------------------------------
// qk projection via mma.sync.  out[b][n][comp*64+o] (2-way bf16 split of
// W@in + bias).  3-way split of W and input -> 6 component GEMMs, fp32 accum.
// Grid (16, 8, 2): 128 n-rows per CTA, z = 0:q(y,Wq,bq) 1:k(x,Wk,bk).
// 256 threads = 8 warps, warp owns 16 rows.  K streamed in chunks of 32.
// ---------------------------------------------------------------------------
#define PKC   32
#define PROW  208                      // A/W smem row stride (bytes)
#define PSF   0                        // f32 staging [32 c][132 f]  (16896 B)
#define PSA   16896                    // A split [128 n][3*64 B]    (26624 B)
#define PSW   43520                    // W split [64 o][3*64 B]     (13312 B)
#define P_TOT 56832

__global__ __launch_bounds__(256) void qk_mma_kernel(
    const float* __restrict__ x, const float* __restrict__ y,
    const float* __restrict__ Wq, const float* __restrict__ bq,
    const float* __restrict__ Wk, const float* __restrict__ bk)
{
    extern __shared__ char smem[];
    const uint32_t sbase = smem_u32(smem);
    const int which = blockIdx.z;
    const float* in   = which ? x  : y;
    const float* W    = which ? Wk : Wq;
    const float* bias = which ? bk : bq;
    __nv_bfloat16* out = which ? g_ks : g_qs;

    const int t    = threadIdx.x;
    const int wid  = t >> 5;
    const int lane = t & 31;
    const int nb   = blockIdx.x * 128;
    const int b    = blockIdx.y;
    const int r0   = wid * 16;

    float* sf32 = (float*)(smem + PSF);

    float acc[8][4];
    #pragma unroll
    for (int nt = 0; nt < 8; nt++)
        #pragma unroll
        for (int i = 0; i < 4; i++) acc[nt][i] = 0.0f;

    for (int kc = 0; kc < 16; kc++) {
        __syncthreads();   // previous chunk's fragments consumed

        // stage input f32 tile [32 c][128 n]
        #pragma unroll
        for (int i = 0; i < 4; i++) {
            int id = t + i * 256;
            int c  = id >> 5;
            int n4 = (id & 31) * 4;
            *(float4*)&sf32[c * 132 + n4] =
                *(const float4*)&in[((b * CCH + kc * PKC + c) * NN) + nb + n4];
        }
        // W chunk: convert directly [64 o][32 c] -> 3-way split
        {
            int o  = t >> 2;
            int c8 = (t & 3) * 8;
            float4 wa = *(const float4*)&W[o * CCH + kc * PKC + c8];
            float4 wb = *(const float4*)&W[o * CCH + kc * PKC + c8 + 4];
            float v[8] = {wa.x, wa.y, wa.z, wa.w, wb.x, wb.y, wb.z, wb.w};
            uint32_t hp[4], mp[4], lp[4];
            #pragma unroll
            for (int j = 0; j < 4; j++) {
                float v0 = v[2*j], v1 = v[2*j+1];
                __nv_bfloat16 h0 = __float2bfloat16(v0);
                float r0f = v0 - __bfloat162float(h0);
                __nv_bfloat16 m0 = __float2bfloat16(r0f);
                __nv_bfloat16 l0 = __float2bfloat16(r0f - __bfloat162float(m0));
                __nv_bfloat16 h1 = __float2bfloat16(v1);
                float r1f = v1 - __bfloat162float(h1);
                __nv_bfloat16 m1 = __float2bfloat16(r1f);
                __nv_bfloat16 l1 = __float2bfloat16(r1f - __bfloat162float(m1));
                hp[j] = us_of(h0) | (us_of(h1) << 16);
                mp[j] = us_of(m0) | (us_of(m1) << 16);
                lp[j] = us_of(l0) | (us_of(l1) << 16);
            }
            char* wrow = smem + PSW + o * PROW + c8 * 2;
            *(uint4*)(wrow)       = make_uint4(hp[0], hp[1], hp[2], hp[3]);
            *(uint4*)(wrow + 64)  = make_uint4(mp[0], mp[1], mp[2], mp[3]);
            *(uint4*)(wrow + 128) = make_uint4(lp[0], lp[1], lp[2], lp[3]);
        }
        __syncthreads();   // staging + W ready

        // transpose-convert A: row n = t>>1, c-half ch = (t&1)*16
        {
            int n  = t >> 1;
            int ch = (t & 1) * 16;
            float v[16];
            #pragma unroll
            for (int j = 0; j < 16; j++) v[j] = sf32[(ch + j) * 132 + n];
            uint32_t hp[8], mp[8], lp[8];
            #pragma unroll
            for (int j = 0; j < 8; j++) {
                float v0 = v[2*j], v1 = v[2*j+1];
                __nv_bfloat16 h0 = __float2bfloat16(v0);
                float r0f = v0 - __bfloat162float(h0);
                __nv_bfloat16 m0 = __float2bfloat16(r0f);
                __nv_bfloat16 l0 = __float2bfloat16(r0f - __bfloat162float(m0));
                __nv_bfloat16 h1 = __float2bfloat16(v1);
                float r1f = v1 - __bfloat162float(h1);
                __nv_bfloat16 m1 = __float2bfloat16(r1f);
                __nv_bfloat16 l1 = __float2bfloat16(r1f - __bfloat162float(m1));
                hp[j] = us_of(h0) | (us_of(h1) << 16);
                mp[j] = us_of(m0) | (us_of(m1) << 16);
                lp[j] = us_of(l0) | (us_of(l1) << 16);
            }
            char* arow = smem + PSA + n * PROW + ch * 2;
            *(uint4*)(arow)            = make_uint4(hp[0], hp[1], hp[2], hp[3]);
            *(uint4*)(arow + 16)       = make_uint4(hp[4], hp[5], hp[6], hp[7]);
            *(uint4*)(arow + 64)       = make_uint4(mp[0], mp[1], mp[2], mp[3]);
            *(uint4*)(arow + 64 + 16)  = make_uint4(mp[4], mp[5], mp[6], mp[7]);
            *(uint4*)(arow + 128)      = make_uint4(lp[0], lp[1], lp[2], lp[3]);
            *(uint4*)(arow + 128 + 16) = make_uint4(lp[4], lp[5], lp[6], lp[7]);
        }
        __syncthreads();   // A + W split tiles ready

        // A fragments: a[comp][ks][4]
        uint32_t a[3][2][4];
        {
            uint32_t aaddr = sbase + PSA + (uint32_t)(r0 + (lane & 15)) * PROW
                           + ((lane >> 4) & 1) * 16;
            #pragma unroll
            for (int c = 0; c < 3; c++)
                #pragma unroll
                for (int ks = 0; ks < 2; ks++)
                    LDSM_X4(a[c][ks][0], a[c][ks][1], a[c][ks][2], a[c][ks][3],
                            aaddr + c * 64 + ks * 32);
        }
        const uint32_t wlane = sbase + PSW + (uint32_t)((lane & 7)) * PROW
                             + ((lane >> 3) & 1) * 16;
        #pragma unroll
        for (int nt = 0; nt < 8; nt++) {
            uint32_t w[3][2][2];
            uint32_t waddr = wlane + (uint32_t)nt * (8 * PROW);
            #pragma unroll
            for (int c = 0; c < 3; c++)
                #pragma unroll
                for (int ks = 0; ks < 2; ks++)
                    LDSM_X2(w[c][ks][0], w[c][ks][1], waddr + c * 64 + ks * 32);
            #pragma unroll
            for (int ks = 0; ks < 2; ks++) {
                mma_bf16(acc[nt][0], acc[nt][1], acc[nt][2], acc[nt][3],
                         a[0][ks][0], a[0][ks][1], a[0][ks][2], a[0][ks][3],
                         w[0][ks][0], w[0][ks][1]);
                mma_bf16(acc[nt][0], acc[nt][1], acc[nt][2], acc[nt][3],
                         a[0][ks][0], a[0][ks][1], a[0][ks][2], a[0][ks][3],
                         w[1][ks][0], w[1][ks][1]);
                mma_bf16(acc[nt][0], acc[nt][1], acc[nt][2], acc[nt][3],
                         a[1][ks][0], a[1][ks][1], a[1][ks][2], a[1][ks][3],
                         w[0][ks][0], w[0][ks][1]);
                mma_bf16(acc[nt][0], acc[nt][1], acc[nt][2], acc[nt][3],
                         a[1][ks][0], a[1][ks][1], a[1][ks][2], a[1][ks][3],
                         w[1][ks][0], w[1][ks][1]);
                mma_bf16(acc[nt][0], acc[nt][1], acc[nt][2], acc[nt][3],
                         a[0][ks][0], a[0][ks][1], a[0][ks][2], a[0][ks][3],
                         w[2][ks][0], w[2][ks][1]);
                mma_bf16(acc[nt][0], acc[nt][1], acc[nt][2], acc[nt][3],
                         a[2][ks][0], a[2][ks][1], a[2][ks][2], a[2][ks][3],
                         w[0][ks][0], w[0][ks][1]);
            }
        }
    }

    // epilogue: bias, 2-way split, store
    const int g = lane >> 2;
    const int cpair = (lane & 3) * 2;
    const int n0 = nb + r0 + g;
    uint32_t* o0p = (uint32_t*)(out + ((size_t)(b * NN + n0)) * 128);
    uint32_t* o1p = (uint32_t*)(out + ((size_t)(b * NN + n0 + 8)) * 128);
    #pragma unroll
    for (int nt = 0; nt < 8; nt++) {
        int o = nt * 8 + cpair;
        float b0 = bias[o], b1 = bias[o + 1];
        float v00 = acc[nt][0] + b0, v01 = acc[nt][1] + b1;
        float v10 = acc[nt][2] + b0, v11 = acc[nt][3] + b1;
        __nv_bfloat16 h00 = __float2bfloat16(v00);
        __nv_bfloat16 m00 = __float2bfloat16(v00 - __bfloat162float(h00));
        __nv_bfloat16 h01 = __float2bfloat16(v01);
        __nv_bfloat16 m01 = __float2bfloat16(v01 - __bfloat162float(h01));
        __nv_bfloat16 h10 = __float2bfloat16(v10);
        __nv_bfloat16 m10 = __float2bfloat16(v10 - __bfloat162float(h10));
        __nv_bfloat16 h11 = __float2bfloat16(v11);
        __nv_bfloat16 m11 = __float2bfloat16(v11 - __bfloat162float(h11));
        o0p[o >> 1]        = us_of(h00) | (us_of(h01) << 16);
        o0p[(64 + o) >> 1] = us_of(m00) | (us_of(m01) << 16);
        o1p[o >> 1]        = us_of(h10) | (us_of(h11) << 16);
        o1p[(64 + o) >> 1] = us_of(m10) | (us_of(m11) << 16);
    }
}

// ---------------------------------------------------------------------------
// Attention via mma.sync bf16, recompute softmax (no rescale pass):
// phase A (it 0..15): energy tiles -> row sums of exp(e) only.
// phase B (it 16..31): recompute, store exp(e)*invS directly.
// CTA = 128 q-rows x 2048 cols.  8 warps x 16 rows.  A frags persistent.
// ---------------------------------------------------------------------------
#define QROW  272
#define SQ    0
#define SK0   34816
#define SK1   69632
#define SM_TOTAL 104448

__global__ __launch_bounds__(256, 1) void attention_mma_kernel(float* __restrict__ att)
{
    extern __shared__ char smem[];
    const uint32_t sb = smem_u32(smem);
    const int t    = threadIdx.x;
    const int wid  = t >> 5;
    const int lane = t & 31;
    const int nb   = blockIdx.x * 128;
    const int b    = blockIdx.y;
    const int r0   = wid * 16;

    // issue k-tile 0 loads (cp.async), then q tile (plain)
    {
        const char* ksrc = (const char*)(g_ks + ((size_t)(b * NN)) * 128);
        #pragma unroll
        for (int i = 0; i < 8; i++) {
            int id  = t + i * 256;
            int row = id >> 4, c16 = id & 15;
            CP_ASYNC16(sb + SK0 + row * QROW + c16 * 16, ksrc + row * 256 + c16 * 16);
        }
        CP_COMMIT();
        const char* qsrc = (const char*)(g_qs + ((size_t)(b * NN + nb)) * 128);
        #pragma unroll
        for (int i = 0; i < 8; i++) {
            int id  = t + i * 256;
            int row = id >> 4, c16 = id & 15;
            *(uint4*)(smem + SQ + row * QROW + c16 * 16) =
                *(const uint4*)(qsrc + row * 256 + c16 * 16);
        }
    }
    __syncthreads();

    // persistent A fragments: a[comp][kstep][4]
    uint32_t a[2][4][4];
    {
        uint32_t qaddr = sb + SQ + (uint32_t)(r0 + (lane & 15)) * QROW + ((lane >> 4) & 1) * 16;
        #pragma unroll
        for (int c = 0; c < 2; c++)
            #pragma unroll
            for (int ks = 0; ks < 4; ks++)
                LDSM_X4(a[c][ks][0], a[c][ks][1], a[c][ks][2], a[c][ks][3],
                        qaddr + c * 128 + ks * 32);
    }

    const uint32_t kb_lane = (uint32_t)((lane & 7) * QROW + ((lane >> 3) & 1) * 16);
    const int g = lane >> 2;
    const int cpair = (lane & 3) * 2;
    float s_lo = 0.0f, s_hi = 0.0f, inv_lo = 0.0f, inv_hi = 0.0f;
    float* rowp0 = att + ((size_t)(b * NN + nb + r0 + g)) * NN;
    float* rowp1 = rowp0 + 8 * NN;

    for (int it = 0; it < 32; it++) {
        const int mt = it & 15;
        if (it < 31) {   // prefetch tile (it+1)&15 into buffer (it+1)&1
            const char* ksrc = (const char*)(g_ks + ((size_t)(b * NN + ((it + 1) & 15) * 128)) * 128);
            uint32_t dst = sb + (((it + 1) & 1) ? SK1 : SK0);
            #pragma unroll
            for (int i = 0; i < 8; i++) {
                int id  = t + i * 256;
                int row = id >> 4, c16 = id & 15;
                CP_ASYNC16(dst + row * QROW + c16 * 16, ksrc + row * 256 + c16 * 16);
            }
            CP_COMMIT();
            asm volatile("cp.async.wait_group 1;" ::: "memory");
        } else {
            asm volatile("cp.async.wait_group 0;" ::: "memory");
        }
        __syncthreads();

        const uint32_t kbase = sb + ((it & 1) ? SK1 : SK0) + kb_lane;
        const int mcol = mt * 128;

        #pragma unroll 4
        for (int nt = 0; nt < 16; nt++) {
            uint32_t bb[2][4][2];
            uint32_t baddr = kbase + (uint32_t)nt * (8 * QROW);
            #pragma unroll
            for (int c = 0; c < 2; c++)
                #pragma unroll
                for (int ks = 0; ks < 4; ks++)
                    LDSM_X2(bb[c][ks][0], bb[c][ks][1], baddr + c * 128 + ks * 32);

            float c0 = 0.f, c1 = 0.f, c2 = 0.f, c3 = 0.f;
            #pragma unroll
            for (int ks = 0; ks < 4; ks++) {
                mma_bf16(c0, c1, c2, c3, a[0][ks][0], a[0][ks][1], a[0][ks][2], a[0][ks][3],
                         bb[0][ks][0], bb[0][ks][1]);
                mma_bf16(c0, c1, c2, c3, a[0][ks][0], a[0][ks][1], a[0][ks][2], a[0][ks][3],
                         bb[1][ks][0], bb[1][ks][1]);
                mma_bf16(c0, c1, c2, c3, a[1][ks][0], a[1][ks][1], a[1][ks][2], a[1][ks][3],
                         bb[0][ks][0], bb[0][ks][1]);
                mma_bf16(c0, c1, c2, c3, a[1][ks][0], a[1][ks][1], a[1][ks][2], a[1][ks][3],
                         bb[1][ks][0], bb[1][ks][1]);
            }

            float e0 = __expf(c0), e1 = __expf(c1);
            float e2 = __expf(c2), e3 = __expf(c3);
            if (it < 16) {
                s_lo += e0 + e1;
                s_hi += e2 + e3;
            } else {
                int col = mcol + nt * 8 + cpair;
                *(float2*)(rowp0 + col) = make_float2(e0 * inv_lo, e1 * inv_lo);
                *(float2*)(rowp1 + col) = make_float2(e2 * inv_hi, e3 * inv_hi);
            }
        }
        __syncthreads();

        if (it == 15) {   // phase boundary: reduce quad sums -> invS
            s_lo += __shfl_xor_sync(0xffffffffu, s_lo, 1);
            s_lo += __shfl_xor_sync(0xffffffffu, s_lo, 2);
            s_hi += __shfl_xor_sync(0xffffffffu, s_hi, 1);
            s_hi += __shfl_xor_sync(0xffffffffu, s_hi, 2);
            inv_lo = 1.0f / s_lo;
            inv_hi = 1.0f / s_hi;
        }
    }
}

// ---------------------------------------------------------------------------
// v projection (slow path, gamma != 0 only), internal loop over output chunk
// ---------------------------------------------------------------------------
__global__ __launch_bounds__(128) void v_kernel(
    const float* __restrict__ in, const float* __restrict__ W,
    const float* __restrict__ bias, const float* __restrict__ gate)
{
    if (gate[0] == 0.0f) return;
    const int t  = threadIdx.x;
    const int tx = t & 7;
    const int ty = t >> 3;
    const int n0 = tx * 8;
    const int o0 = ty * 4;
    const int nb = blockIdx.x * 64;
    const int b  = blockIdx.y;

    __shared__ float inT[32][68];
    __shared__ float wT [32][68];

    for (int obi = 0; obi < 8; obi++) {
        const int ob = obi * 64;
        float acc[4][8];
        #pragma unroll
        for (int o = 0; o < 4; o++)
            #pragma unroll
            for (int n = 0; n < 8; n++) acc[o][n] = 0.0f;

        for (int c0 = 0; c0 < CCH; c0 += 32) {
            __syncthreads();
            #pragma unroll
            for (int i = 0; i < 4; i++) {
                int l  = t + i * 128;
                int cc = l >> 4;
                int n4 = (l & 15) * 4;
                *(float4*)&inT[cc][n4] =
                    *(const float4*)&in[((b * CCH + c0 + cc) * NN) + nb + n4];
            }
            #pragma unroll
            for (int i = 0; i < 4; i++) {
                int l  = t + i * 128;
                int o  = l >> 3;
                int c4 = (l & 7) * 4;
                float4 w4 = *(const float4*)&W[(ob + o) * CCH + c0 + c4];
                wT[c4 + 0][o] = w4.x; wT[c4 + 1][o] = w4.y;
                wT[c4 + 2][o] = w4.z; wT[c4 + 3][o] = w4.w;
            }
            __syncthreads();
            #pragma unroll 8
            for (int cc = 0; cc < 32; cc++) {
                float4 wv = *(const float4*)&wT[cc][o0];
                float4 a0 = *(const float4*)&inT[cc][n0];
                float4 a1 = *(const float4*)&inT[cc][n0 + 4];
                float w[4] = {wv.x, wv.y, wv.z, wv.w};
                float v[8] = {a0.x, a0.y, a0.z, a0.w, a1.x, a1.y, a1.z, a1.w};
                #pragma unroll
                for (int o = 0; o < 4; o++)
                    #pragma unroll
                    for (int n = 0; n < 8; n++)
                        acc[o][n] = fmaf(w[o], v[n], acc[o][n]);
            }
        }

        #pragma unroll
        for (int o = 0; o < 4; o++) {
            int row = ob + o0 + o;
            float bb = bias[row];
            float* op = &g_v[((size_t)b * CCH + row) * NN + nb + n0];
            *(float4*)op       = make_float4(acc[o][0]+bb, acc[o][1]+bb, acc[o][2]+bb, acc[o][3]+bb);
            *(float4*)(op + 4) = make_float4(acc[o][4]+bb, acc[o][5]+bb, acc[o][6]+bb, acc[o][7]+bb);
        }
    }
}

// ---------------------------------------------------------------------------
// AV GEMM (slow path), internal loop over c chunk
// ---------------------------------------------------------------------------
__global__ __launch_bounds__(128) void av_kernel(const float* __restrict__ att,
                                                 const float* __restrict__ gate)
{
    if (gate[0] == 0.0f) return;
    const int t  = threadIdx.x;
    const int tx = t & 7;
    const int ty = t >> 3;
    const int n0 = tx * 8;
    const int c0 = ty * 4;
    const int nb = blockIdx.x * 64;
    const int b  = blockIdx.y;

    __shared__ float vT[32][68];
    __shared__ float aT[32][68];

    for (int cbi = 0; cbi < 8; cbi++) {
        const int cb = cbi * 64;
        float acc[4][8];
        #pragma unroll
        for (int o = 0; o < 4; o++)
            #pragma unroll
            for (int n = 0; n < 8; n++) acc[o][n] = 0.0f;

        for (int mc = 0; mc < NN; mc += 32) {
            __syncthreads();
            #pragma unroll
            for (int i = 0; i < 4; i++) {
                int l  = t + i * 128;
                int c  = l >> 3;
                int m4 = (l & 7) * 4;
                float4 v = *(const float4*)&g_v[((size_t)b * CCH + cb + c) * NN + mc + m4];
                vT[m4 + 0][c] = v.x; vT[m4 + 1][c] = v.y;
                vT[m4 + 2][c] = v.z; vT[m4 + 3][c] = v.w;
                float4 aa = *(const float4*)&att[((size_t)(b * NN + nb + c)) * NN + mc + m4];
                aT[m4 + 0][c] = aa.x; aT[m4 + 1][c] = aa.y;
                aT[m4 + 2][c] = aa.z; aT[m4 + 3][c] = aa.w;
            }
            __syncthreads();
            #pragma unroll 8
            for (int mm = 0; mm < 32; mm++) {
                float4 vv = *(const float4*)&vT[mm][c0];
                float4 a0 = *(const float4*)&aT[mm][n0];
                float4 a1 = *(const float4*)&aT[mm][n0 + 4];
                float v[4] = {vv.x, vv.y, vv.z, vv.w};
                float aa[8] = {a0.x, a0.y, a0.z, a0.w, a1.x, a1.y, a1.z, a1.w};
                #pragma unroll
                for (int o = 0; o < 4; o++)
                    #pragma unroll
                    for (int n = 0; n < 8; n++)
                        acc[o][n] = fmaf(v[o], aa[n], acc[o][n]);
            }
        }

        #pragma unroll
        for (int o = 0; o < 4; o++) {
            float* op = &g_av[((size_t)b * CCH + cb + c0 + o) * NN + nb + n0];
            *(float4*)op       = make_float4(acc[o][0], acc[o][1], acc[o][2], acc[o][3]);
            *(float4*)(op + 4) = make_float4(acc[o][4], acc[o][5], acc[o][6], acc[o][7]);
        }
    }
}

// ---------------------------------------------------------------------------
// Epilogue: out = gamma*AV + x (gamma==0 fast path: out = x), grid-stride
// ---------------------------------------------------------------------------
__global__ void epilogue_kernel(const float* __restrict__ x,
                                const float* __restrict__ gamma,
                                float* __restrict__ out)
{
    const int stride = gridDim.x * blockDim.x;
    const float g = gamma[0];
    for (int i = blockIdx.x * blockDim.x + threadIdx.x; i < OUT_OFF / 4; i += stride) {
        float4 xv = ((const float4*)x)[i];
        if (g != 0.0f) {
            float4 av = ((const float4*)g_av)[i];
            xv.x = fmaf(g, av.x, xv.x);
            xv.y = fmaf(g, av.y, xv.y);
            xv.z = fmaf(g, av.z, xv.z);
            xv.w = fmaf(g, av.w, xv.w);
        }
        ((float4*)out)[i] = xv;
    }
}

// ---------------------------------------------------------------------------
extern "C" void kernel_launch(void* const* d_in, const int* in_sizes, int n_in,
                              void* d_out, int out_size)
{
    (void)in_sizes; (void)n_in; (void)out_size;
    const float* x     = (const float*)d_in[0];
    const float* y     = (const float*)d_in[1];
    const float* Wq    = (const float*)d_in[2];
    const float* bq    = (const float*)d_in[3];
    const float* Wk    = (const float*)d_in[4];
    const float* bk    = (const float*)d_in[5];
    const float* Wv    = (const float*)d_in[6];
    const float* bv    = (const float*)d_in[7];
    const float* gamma = (const float*)d_in[8];

    float* out = (float*)d_out;
    float* att = out + OUT_OFF;

    cudaFuncSetAttribute(qk_mma_kernel,
                         cudaFuncAttributeMaxDynamicSharedMemorySize, P_TOT);
    cudaFuncSetAttribute(attention_mma_kernel,
                         cudaFuncAttributeMaxDynamicSharedMemorySize, SM_TOTAL);

    qk_mma_kernel<<<dim3(NN/128, BB, 2), 256, P_TOT>>>(x, y, Wq, bq, Wk, bk);
    v_kernel<<<dim3(NN/64, BB), 128>>>(y, Wv, bv, gamma);
    attention_mma_kernel<<<dim3(16, BB), 256, SM_TOTAL>>>(att);
    av_kernel<<<dim3(NN/64, BB), 128>>>(att, gamma);
    epilogue_kernel<<<1184, 256>>>(x, gamma, out);
}

// round 6
// speedup vs baseline: 1.1834x; 1.1834x over previous
#include <cuda_runtime.h>
#include <cuda_bf16.h>
#include <math.h>
#include <cstdint>

// Problem constants
#define BB   8
#define CCH  512
#define C8   64
#define NN   2048
#define OUT_OFF (BB*CCH*NN)   // start of attention region in d_out (floats)

typedef unsigned long long u64;

// Scratch: q/k as 2-way bf16 split [b][n][comp*64 + o], comp 0=hi, 1=mid
__device__ __nv_bfloat16 g_qs[BB*NN*128];
__device__ __nv_bfloat16 g_ks[BB*NN*128];
__device__ float g_v[BB*CCH*NN];           // slow path only (gamma != 0)

// ---- packed f32x2 helpers ------------------------------------------------
__device__ __forceinline__ u64 pack2(float x) {
    u64 r; asm("mov.b64 %0, {%1, %1};" : "=l"(r) : "f"(x)); return r;
}
__device__ __forceinline__ void ffma2(u64& d, u64 a, u64 b) {
    asm("fma.rn.f32x2 %0, %1, %2, %3;" : "=l"(d) : "l"(a), "l"(b), "l"(d));
}
__device__ __forceinline__ float2 unpack2(u64 v) {
    float2 f; asm("mov.b64 {%0, %1}, %2;" : "=f"(f.x), "=f"(f.y) : "l"(v)); return f;
}

// ---- sm_80-class tensor helpers (legal on plain sm_103 target) -----------
__device__ __forceinline__ uint32_t smem_u32(const void* p) {
    uint32_t a;
    asm("{ .reg .u64 t; cvta.to.shared.u64 t, %1; cvt.u32.u64 %0, t; }" : "=r"(a) : "l"(p));
    return a;
}
#define LDSM_X4(r0, r1, r2, r3, addr) \
    asm volatile("ldmatrix.sync.aligned.m8n8.x4.shared.b16 {%0,%1,%2,%3}, [%4];" \
        : "=r"(r0), "=r"(r1), "=r"(r2), "=r"(r3) : "r"(addr))
#define LDSM_X2(r0, r1, addr) \
    asm volatile("ldmatrix.sync.aligned.m8n8.x2.shared.b16 {%0,%1}, [%2];" \
        : "=r"(r0), "=r"(r1) : "r"(addr))
#define CP_ASYNC16(dst, src) \
    asm volatile("cp.async.cg.shared.global [%0], [%1], 16;" :: "r"(dst), "l"(src) : "memory")
#define CP_COMMIT() asm volatile("cp.async.commit_group;" ::: "memory")

__device__ __forceinline__ void mma_bf16(float& c0, float& c1, float& c2, float& c3,
                                         uint32_t a0, uint32_t a1, uint32_t a2, uint32_t a3,
                                         uint32_t b0, uint32_t b1) {
    asm volatile(
        "mma.sync.aligned.m16n8k16.row.col.f32.bf16.bf16.f32 "
        "{%0,%1,%2,%3}, {%4,%5,%6,%7}, {%8,%9}, {%0,%1,%2,%3};"
        : "+f"(c0), "+f"(c1), "+f"(c2), "+f"(c3)
        : "r"(a0), "r"(a1), "r"(a2), "r"(a3), "r"(b0), "r"(b1));
}

// ---------------------------------------------------------------------------
// Fused q+k projection (FFMA2) -> 2-way bf16 split, layout [b][n][comp*64+o].
// which==1 (k from x) additionally copies x into out region (out = x) so the
// standalone epilogue kernel is unnecessary in the gamma==0 fast path.
// ---------------------------------------------------------------------------
__global__ __launch_bounds__(128, 3) void qk_kernel(
    const float* __restrict__ x, const float* __restrict__ y,
    const float* __restrict__ Wq, const float* __restrict__ bq,
    const float* __restrict__ Wk, const float* __restrict__ bk,
    float* __restrict__ outx)
{
    const int which = blockIdx.z;
    const float* in   = which ? x  : y;
    const float* W    = which ? Wk : Wq;
    const float* bias = which ? bk : bq;

    const int t  = threadIdx.x;
    const int tx = t & 15;
    const int ty = t >> 4;
    const int n0 = tx * 8;
    const int o0 = ty * 8;
    const int nb = blockIdx.x * 128;
    const int b  = blockIdx.y;

    __shared__ float wt[32][68];
    __shared__ float it[32][128];

    u64 acc[8][4];
    #pragma unroll
    for (int j = 0; j < 8; j++)
        #pragma unroll
        for (int i = 0; i < 4; i++) acc[j][i] = 0ull;

    for (int c0 = 0; c0 < CCH; c0 += 32) {
        __syncthreads();
        #pragma unroll
        for (int i = 0; i < 4; i++) {
            int l  = t + i * 128;
            int o  = l >> 3;
            int c4 = (l & 7) * 4;
            float4 w4 = *(const float4*)&W[o * CCH + c0 + c4];
            wt[c4 + 0][o] = w4.x; wt[c4 + 1][o] = w4.y;
            wt[c4 + 2][o] = w4.z; wt[c4 + 3][o] = w4.w;
        }
        #pragma unroll
        for (int i = 0; i < 8; i++) {
            int l  = t + i * 128;
            int cc = l >> 5;
            int n4 = (l & 31) * 4;
            size_t gidx = ((size_t)(b * CCH + c0 + cc) * NN) + nb + n4;
            float4 v = *(const float4*)&in[gidx];
            *(float4*)&it[cc][n4] = v;
            if (which) *(float4*)&outx[gidx] = v;   // out = x (residual copy)
        }
        __syncthreads();

        #pragma unroll 4
        for (int cc = 0; cc < 32; cc++) {
            float4 w0 = *(const float4*)&wt[cc][o0];
            float4 w1 = *(const float4*)&wt[cc][o0 + 4];
            u64 wp[8] = {pack2(w0.x), pack2(w0.y), pack2(w0.z), pack2(w0.w),
                         pack2(w1.x), pack2(w1.y), pack2(w1.z), pack2(w1.w)};
            ulonglong2 ia = *(const ulonglong2*)&it[cc][n0];
            ulonglong2 ib = *(const ulonglong2*)&it[cc][n0 + 4];
            u64 iv[4] = {ia.x, ia.y, ib.x, ib.y};
            #pragma unroll
            for (int j = 0; j < 8; j++)
                #pragma unroll
                for (int i = 0; i < 4; i++)
                    ffma2(acc[j][i], wp[j], iv[i]);
        }
    }

    float val[8][8];
    #pragma unroll
    for (int j = 0; j < 8; j++) {
        float bb = bias[o0 + j];
        float2 p0 = unpack2(acc[j][0]);
        float2 p1 = unpack2(acc[j][1]);
        float2 p2 = unpack2(acc[j][2]);
        float2 p3 = unpack2(acc[j][3]);
        val[j][0] = p0.x + bb; val[j][1] = p0.y + bb;
        val[j][2] = p1.x + bb; val[j][3] = p1.y + bb;
        val[j][4] = p2.x + bb; val[j][5] = p2.y + bb;
        val[j][6] = p3.x + bb; val[j][7] = p3.y + bb;
    }

    #pragma unroll
    for (int i = 0; i < 8; i++) {
        uint32_t hi[4], mi[4];
        #pragma unroll
        for (int jp = 0; jp < 4; jp++) {
            float v0 = val[2*jp][i], v1 = val[2*jp+1][i];
            __nv_bfloat16 h0 = __float2bfloat16(v0);
            __nv_bfloat16 m0 = __float2bfloat16(v0 - __bfloat162float(h0));
            __nv_bfloat16 h1 = __float2bfloat16(v1);
            __nv_bfloat16 m1 = __float2bfloat16(v1 - __bfloat162float(h1));
            hi[jp] = (uint32_t)__bfloat16_as_ushort(h0) | ((uint32_t)__bfloat16_as_ushort(h1) << 16);
            mi[jp] = (uint32_t)__bfloat16_as_ushort(m0) | ((uint32_t)__bfloat16_as_ushort(m1) << 16);
        }
        __nv_bfloat16* rowp = (which ? g_ks : g_qs)
                            + ((size_t)(b * NN + nb + n0 + i)) * 128 + o0;
        *(uint4*)(rowp)      = make_uint4(hi[0], hi[1], hi[2], hi[3]);
        *(uint4*)(rowp + 64) = make_uint4(mi[0], mi[1], mi[2], mi[3]);
    }
}

// ---------------------------------------------------------------------------
// Attention via mma.sync bf16 (m16n8k16), 3 split-GEMMs {hh, hm, mh}
// (mid*mid dropped: ~3e-5 abs error in e, 30x under tolerance).
// CTA = 128 q-rows x 2048 cols. 8 warps x 16 rows. A frags persistent.
// Pass 1: store exp(e) + row sums.  Rescale pass: L2-hot RMW by own warp.
// ---------------------------------------------------------------------------
#define QROW  272
#define SQ    0
#define SK0   34816
#define SK1   69632
#define SINV  104448
#define SM_TOTAL 104960

__global__ __launch_bounds__(256, 1) void attention_mma_kernel(float* __restrict__ att)
{
    extern __shared__ char smem[];
    const uint32_t sb = smem_u32(smem);
    const int t    = threadIdx.x;
    const int wid  = t >> 5;
    const int lane = t & 31;
    const int nb   = blockIdx.x * 128;
    const int b    = blockIdx.y;
    const int r0   = wid * 16;

    // issue k-tile 0 loads (cp.async), then q tile (plain)
    {
        const char* ksrc = (const char*)(g_ks + ((size_t)(b * NN)) * 128);
        #pragma unroll
        for (int i = 0; i < 8; i++) {
            int id  = t + i * 256;
            int row = id >> 4, c16 = id & 15;
            CP_ASYNC16(sb + SK0 + row * QROW + c16 * 16, ksrc + row * 256 + c16 * 16);
        }
        CP_COMMIT();
        const char* qsrc = (const char*)(g_qs + ((size_t)(b * NN + nb)) * 128);
        #pragma unroll
        for (int i = 0; i < 8; i++) {
            int id  = t + i * 256;
            int row = id >> 4, c16 = id & 15;
            *(uint4*)(smem + SQ + row * QROW + c16 * 16) =
                *(const uint4*)(qsrc + row * 256 + c16 * 16);
        }
    }
    __syncthreads();

    // persistent A fragments: a[comp][kstep][4]
    uint32_t a[2][4][4];
    {
        uint32_t qaddr = sb + SQ + (uint32_t)(r0 + (lane & 15)) * QROW + ((lane >> 4) & 1) * 16;
        #pragma unroll
        for (int c = 0; c < 2; c++)
            #pragma unroll
            for (int ks = 0; ks < 4; ks++)
                LDSM_X4(a[c][ks][0], a[c][ks][1], a[c][ks][2], a[c][ks][3],
                        qaddr + c * 128 + ks * 32);
    }

    const uint32_t kb_lane = (uint32_t)((lane & 7) * QROW + ((lane >> 3) & 1) * 16);
    const int g = lane >> 2;
    const int cpair = (lane & 3) * 2;
    float s_lo = 0.0f, s_hi = 0.0f;
    float* rowp0 = att + ((size_t)(b * NN + nb + r0 + g)) * NN;
    float* rowp1 = rowp0 + 8 * NN;

    for (int mt = 0; mt < 16; mt++) {
        if (mt + 1 < 16) {
            const char* ksrc = (const char*)(g_ks + ((size_t)(b * NN + (mt + 1) * 128)) * 128);
            uint32_t dst = sb + (((mt + 1) & 1) ? SK1 : SK0);
            #pragma unroll
            for (int i = 0; i < 8; i++) {
                int id  = t + i * 256;
                int row = id >> 4, c16 = id & 15;
                CP_ASYNC16(dst + row * QROW + c16 * 16, ksrc + row * 256 + c16 * 16);
            }
            CP_COMMIT();
            asm volatile("cp.async.wait_group 1;" ::: "memory");
        } else {
            asm volatile("cp.async.wait_group 0;" ::: "memory");
        }
        __syncthreads();

        const uint32_t kbase = sb + ((mt & 1) ? SK1 : SK0) + kb_lane;
        const int mcol = mt * 128;

        #pragma unroll 4
        for (int nt = 0; nt < 16; nt++) {
            uint32_t bb[2][4][2];
            uint32_t baddr = kbase + (uint32_t)nt * (8 * QROW);
            #pragma unroll
            for (int c = 0; c < 2; c++)
                #pragma unroll
                for (int ks = 0; ks < 4; ks++)
                    LDSM_X2(bb[c][ks][0], bb[c][ks][1], baddr + c * 128 + ks * 32);

            float c0 = 0.f, c1 = 0.f, c2 = 0.f, c3 = 0.f;
            #pragma unroll
            for (int ks = 0; ks < 4; ks++) {
                mma_bf16(c0, c1, c2, c3, a[0][ks][0], a[0][ks][1], a[0][ks][2], a[0][ks][3],
                         bb[0][ks][0], bb[0][ks][1]);
                mma_bf16(c0, c1, c2, c3, a[0][ks][0], a[0][ks][1], a[0][ks][2], a[0][ks][3],
                         bb[1][ks][0], bb[1][ks][1]);
                mma_bf16(c0, c1, c2, c3, a[1][ks][0], a[1][ks][1], a[1][ks][2], a[1][ks][3],
                         bb[0][ks][0], bb[0][ks][1]);
                // mid*mid dropped (error ~3e-5, tolerance 1e-3)
            }

            float e0 = __expf(c0), e1 = __expf(c1);
            float e2 = __expf(c2), e3 = __expf(c3);
            s_lo += e0 + e1;
            s_hi += e2 + e3;
            int col = mcol + nt * 8 + cpair;
            *(float2*)(rowp0 + col) = make_float2(e0, e1);
            *(float2*)(rowp1 + col) = make_float2(e2, e3);
        }
        __syncthreads();
    }

    // per-row sums: reduce across the 4 lanes of each quad
    s_lo += __shfl_xor_sync(0xffffffffu, s_lo, 1);
    s_lo += __shfl_xor_sync(0xffffffffu, s_lo, 2);
    s_hi += __shfl_xor_sync(0xffffffffu, s_hi, 1);
    s_hi += __shfl_xor_sync(0xffffffffu, s_hi, 2);
    float* invs = (float*)(smem + SINV);
    if ((lane & 3) == 0) {
        invs[r0 + g]     = 1.0f / s_lo;
        invs[r0 + g + 8] = 1.0f / s_hi;
    }
    __syncwarp();

    // rescale own 16 rows (warp-local; L2-hot)
    for (int rr = 0; rr < 16; rr++) {
        float inv = invs[r0 + rr];
        float* rp = att + ((size_t)(b * NN + nb + r0 + rr)) * NN;
        #pragma unroll 4
        for (int it = 0; it < 16; it++) {
            float4* p = (float4*)(rp + (it * 32 + lane) * 4);
            float4 v = *p;
            v.x *= inv; v.y *= inv; v.z *= inv; v.w *= inv;
            *p = v;
        }
    }
}

// ---------------------------------------------------------------------------
// v projection (slow path, gamma != 0 only), internal loop over output chunk
// ---------------------------------------------------------------------------
__global__ __launch_bounds__(128) void v_kernel(
    const float* __restrict__ in, const float* __restrict__ W,
    const float* __restrict__ bias, const float* __restrict__ gate)
{
    if (gate[0] == 0.0f) return;
    const int t  = threadIdx.x;
    const int tx = t & 7;
    const int ty = t >> 3;
    const int n0 = tx * 8;
    const int o0 = ty * 4;
    const int nb = blockIdx.x * 64;
    const int b  = blockIdx.y;

    __shared__ float inT[32][68];
    __shared__ float wT [32][68];

    for (int obi = 0; obi < 8; obi++) {
        const int ob = obi * 64;
        float acc[4][8];
        #pragma unroll
        for (int o = 0; o < 4; o++)
            #pragma unroll
            for (int n = 0; n < 8; n++) acc[o][n] = 0.0f;

        for (int c0 = 0; c0 < CCH; c0 += 32) {
            __syncthreads();
            #pragma unroll
            for (int i = 0; i < 4; i++) {
                int l  = t + i * 128;
                int cc = l >> 4;
                int n4 = (l & 15) * 4;
                *(float4*)&inT[cc][n4] =
                    *(const float4*)&in[((b * CCH + c0 + cc) * NN) + nb + n4];
            }
            #pragma unroll
            for (int i = 0; i < 4; i++) {
                int l  = t + i * 128;
                int o  = l >> 3;
                int c4 = (l & 7) * 4;
                float4 w4 = *(const float4*)&W[(ob + o) * CCH + c0 + c4];
                wT[c4 + 0][o] = w4.x; wT[c4 + 1][o] = w4.y;
                wT[c4 + 2][o] = w4.z; wT[c4 + 3][o] = w4.w;
            }
            __syncthreads();
            #pragma unroll 8
            for (int cc = 0; cc < 32; cc++) {
                float4 wv = *(const float4*)&wT[cc][o0];
                float4 a0 = *(const float4*)&inT[cc][n0];
                float4 a1 = *(const float4*)&inT[cc][n0 + 4];
                float w[4] = {wv.x, wv.y, wv.z, wv.w};
                float v[8] = {a0.x, a0.y, a0.z, a0.w, a1.x, a1.y, a1.z, a1.w};
                #pragma unroll
                for (int o = 0; o < 4; o++)
                    #pragma unroll
                    for (int n = 0; n < 8; n++)
                        acc[o][n] = fmaf(w[o], v[n], acc[o][n]);
            }
        }

        #pragma unroll
        for (int o = 0; o < 4; o++) {
            int row = ob + o0 + o;
            float bb = bias[row];
            float* op = &g_v[((size_t)b * CCH + row) * NN + nb + n0];
            *(float4*)op       = make_float4(acc[o][0]+bb, acc[o][1]+bb, acc[o][2]+bb, acc[o][3]+bb);
            *(float4*)(op + 4) = make_float4(acc[o][4]+bb, acc[o][5]+bb, acc[o][6]+bb, acc[o][7]+bb);
        }
    }
}

// ---------------------------------------------------------------------------
// AV GEMM (slow path): writes out = gamma*(V@att^T) + x directly.
// ---------------------------------------------------------------------------
__global__ __launch_bounds__(128) void av_kernel(const float* __restrict__ att,
                                                 const float* __restrict__ x,
                                                 const float* __restrict__ gate,
                                                 float* __restrict__ out)
{
    const float gm = gate[0];
    if (gm == 0.0f) return;
    const int t  = threadIdx.x;
    const int tx = t & 7;
    const int ty = t >> 3;
    const int n0 = tx * 8;
    const int c0 = ty * 4;
    const int nb = blockIdx.x * 64;
    const int b  = blockIdx.y;

    __shared__ float vT[32][68];
    __shared__ float aT[32][68];

    for (int cbi = 0; cbi < 8; cbi++) {
        const int cb = cbi * 64;
        float acc[4][8];
        #pragma unroll
        for (int o = 0; o < 4; o++)
            #pragma unroll
            for (int n = 0; n < 8; n++) acc[o][n] = 0.0f;

        for (int mc = 0; mc < NN; mc += 32) {
            __syncthreads();
            #pragma unroll
            for (int i = 0; i < 4; i++) {
                int l  = t + i * 128;
                int c  = l >> 3;
                int m4 = (l & 7) * 4;
                float4 v = *(const float4*)&g_v[((size_t)b * CCH + cb + c) * NN + mc + m4];
                vT[m4 + 0][c] = v.x; vT[m4 + 1][c] = v.y;
                vT[m4 + 2][c] = v.z; vT[m4 + 3][c] = v.w;
                float4 aa = *(const float4*)&att[((size_t)(b * NN + nb + c)) * NN + mc + m4];
                aT[m4 + 0][c] = aa.x; aT[m4 + 1][c] = aa.y;
                aT[m4 + 2][c] = aa.z; aT[m4 + 3][c] = aa.w;
            }
            __syncthreads();
            #pragma unroll 8
            for (int mm = 0; mm < 32; mm++) {
                float4 vv = *(const float4*)&vT[mm][c0];
                float4 a0 = *(const float4*)&aT[mm][n0];
                float4 a1 = *(const float4*)&aT[mm][n0 + 4];
                float v[4] = {vv.x, vv.y, vv.z, vv.w};
                float aa[8] = {a0.x, a0.y, a0.z, a0.w, a1.x, a1.y, a1.z, a1.w};
                #pragma unroll
                for (int o = 0; o < 4; o++)
                    #pragma unroll
                    for (int n = 0; n < 8; n++)
                        acc[o][n] = fmaf(v[o], aa[n], acc[o][n]);
            }
        }

        #pragma unroll
        for (int o = 0; o < 4; o++) {
            size_t gidx = ((size_t)b * CCH + cb + c0 + o) * NN + nb + n0;
            float4 x0 = *(const float4*)&x[gidx];
            float4 x1 = *(const float4*)&x[gidx + 4];
            *(float4*)&out[gidx] = make_float4(
                fmaf(gm, acc[o][0], x0.x), fmaf(gm, acc[o][1], x0.y),
                fmaf(gm, acc[o][2], x0.z), fmaf(gm, acc[o][3], x0.w));
            *(float4*)&out[gidx + 4] = make_float4(
                fmaf(gm, acc[o][4], x1.x), fmaf(gm, acc[o][5], x1.y),
                fmaf(gm, acc[o][6], x1.z), fmaf(gm, acc[o][7], x1.w));
        }
    }
}

// ---------------------------------------------------------------------------
extern "C" void kernel_launch(void* const* d_in, const int* in_sizes, int n_in,
                              void* d_out, int out_size)
{
    (void)in_sizes; (void)n_in; (void)out_size;
    const float* x     = (const float*)d_in[0];
    const float* y     = (const float*)d_in[1];
    const float* Wq    = (const float*)d_in[2];
    const float* bq    = (const float*)d_in[3];
    const float* Wk    = (const float*)d_in[4];
    const float* bk    = (const float*)d_in[5];
    const float* Wv    = (const float*)d_in[6];
    const float* bv    = (const float*)d_in[7];
    const float* gamma = (const float*)d_in[8];

    float* out = (float*)d_out;
    float* att = out + OUT_OFF;

    cudaFuncSetAttribute(attention_mma_kernel,
                         cudaFuncAttributeMaxDynamicSharedMemorySize, SM_TOTAL);

    // q = Wq*y+bq, k = Wk*x+bk (split bf16); which==1 also writes out = x
    qk_kernel<<<dim3(NN/128, BB, 2), 128>>>(x, y, Wq, bq, Wk, bk, out);
    // v projection (gated on gamma != 0)
    v_kernel<<<dim3(NN/64, BB), 128>>>(y, Wv, bv, gamma);
    // energy GEMM + softmax -> attention output region
    attention_mma_kernel<<<dim3(16, BB), 256, SM_TOTAL>>>(att);
    // out = gamma*(V@att^T) + x (gated; fast path keeps out = x from qk)
    av_kernel<<<dim3(NN/64, BB), 128>>>(att, x, gamma, out);
}